// round 15
// baseline (speedup 1.0000x reference)
#include <cuda_runtime.h>
#include <cuda_bf16.h>
#include <cuda_fp16.h>
#include <math.h>
#include <stdint.h>

#define BATCH 8
#define SEQ 1024
#define DMODEL 768
#define NHEAD 12
#define HDIM 64
#define MROWS (BATCH*SEQ)

// sqrt(1/sqrt(64) * log2(e)) — applied to BOTH Q and K so S lands in log2 domain
#define QSC2 0.42466089981329596f

// ------------------------- device scratch (no allocs) -----------------------
__device__ __align__(16) __half g_xh[MROWS*DMODEL];       // x fp16 split [M][K]
__device__ __align__(16) __half g_xl[MROWS*DMODEL];
__device__ __align__(16) __half g_wt[4][DMODEL*DMODEL];   // W^T single fp16 [N][K]
__device__ __align__(16) __half g_qh[MROWS*DMODEL];       // Q*QSC2 fp16 split
__device__ __align__(16) __half g_ql[MROWS*DMODEL];
__device__ __align__(16) __half g_kh[MROWS*DMODEL];       // K*QSC2 fp16 SINGLE
__device__ __align__(16) __half g_vh[MROWS*DMODEL];       // V fp16 split [bh][s][d]
__device__ __align__(16) __half g_vl[MROWS*DMODEL];
__device__ __align__(16) __half g_ah[MROWS*DMODEL];       // attn out fp16 split [M][K]
__device__ __align__(16) __half g_al[MROWS*DMODEL];

// ------------------------- helpers ------------------------------------------
__device__ __forceinline__ void mma16h(float c[4], const uint32_t a[4],
                                       uint32_t b0, uint32_t b1) {
    asm volatile("mma.sync.aligned.m16n8k16.row.col.f32.f16.f16.f32 "
        "{%0,%1,%2,%3}, {%4,%5,%6,%7}, {%8,%9}, {%0,%1,%2,%3};"
        : "+f"(c[0]), "+f"(c[1]), "+f"(c[2]), "+f"(c[3])
        : "r"(a[0]), "r"(a[1]), "r"(a[2]), "r"(a[3]), "r"(b0), "r"(b1));
}
__device__ __forceinline__ uint32_t sm_addr(const void* p) {
    return (uint32_t)__cvta_generic_to_shared(p);
}
__device__ __forceinline__ void ldsm_x4(uint32_t& r0, uint32_t& r1, uint32_t& r2,
                                        uint32_t& r3, uint32_t addr) {
    asm volatile("ldmatrix.sync.aligned.m8n8.x4.shared.b16 {%0,%1,%2,%3}, [%4];"
        : "=r"(r0), "=r"(r1), "=r"(r2), "=r"(r3) : "r"(addr));
}
__device__ __forceinline__ void ldsm_x4_t(uint32_t& r0, uint32_t& r1, uint32_t& r2,
                                          uint32_t& r3, uint32_t addr) {
    asm volatile("ldmatrix.sync.aligned.m8n8.x4.trans.shared.b16 {%0,%1,%2,%3}, [%4];"
        : "=r"(r0), "=r"(r1), "=r"(r2), "=r"(r3) : "r"(addr));
}
__device__ __forceinline__ void cp16(void* dst, const void* src) {
    asm volatile("cp.async.cg.shared.global [%0], [%1], 16;"
        :: "r"(sm_addr(dst)), "l"(src));
}
#define CP_COMMIT() asm volatile("cp.async.commit_group;" ::: "memory")
#define CP_WAIT(n)  asm volatile("cp.async.wait_group %0;" :: "n"(n) : "memory")
__device__ __forceinline__ float ex2(float x) {
    float r; asm("ex2.approx.ftz.f32 %0, %1;" : "=f"(r) : "f"(x)); return r;
}
// fp16 round-split of two floats
__device__ __forceinline__ void packsplit_h(float x, float y, uint32_t& H, uint32_t& L) {
    __half2 h = __floats2half2_rn(x, y);
    float2 hf = __half22float2(h);
    __half2 l = __floats2half2_rn(x - hf.x, y - hf.y);
    H = *reinterpret_cast<uint32_t*>(&h);
    L = *reinterpret_cast<uint32_t*>(&l);
}

// ------------------------- prep kernels -------------------------------------
__global__ void __launch_bounds__(256) prep_x(const float* __restrict__ x)
{
    const int i = blockIdx.x * 256 + threadIdx.x;   // float4 index
    float4 v = ((const float4*)x)[i];
    uint32_t H0, L0, H1, L1;
    packsplit_h(v.x, v.y, H0, L0);
    packsplit_h(v.z, v.w, H1, L1);
    ((uint2*)g_xh)[i] = make_uint2(H0, H1);
    ((uint2*)g_xl)[i] = make_uint2(L0, L1);
}

__global__ void __launch_bounds__(256) prep_wt(const float* __restrict__ Wq,
                                               const float* __restrict__ Wk,
                                               const float* __restrict__ Wv,
                                               const float* __restrict__ Wo)
{
    __shared__ float tile[32][33];
    const int wid = blockIdx.z;
    const float* W = (wid == 0) ? Wq : (wid == 1) ? Wk : (wid == 2) ? Wv : Wo;
    const int n0 = blockIdx.x * 32, k0 = blockIdx.y * 32;
    const int tx = threadIdx.x & 31, ty = threadIdx.x >> 5;
    #pragma unroll
    for (int i = 0; i < 32; i += 8)
        tile[ty + i][tx] = W[(size_t)(k0 + ty + i) * DMODEL + n0 + tx];
    __syncthreads();
    #pragma unroll
    for (int i = 0; i < 32; i += 8)
        g_wt[wid][(size_t)(n0 + ty + i) * DMODEL + k0 + tx] =
            __float2half_rn(tile[tx][ty + i]);
}

// ------------------------- fp16 GEMM, 3-stage cp.async ring ------------------
// MODE 0: fused QKV (blockIdx.z)   MODE 4: O proj -> fp32 out
// C = (Ah + Al) * W^T;  2 MMAs per k16 block.
#define GSTR 40
#define GTILE (128*GSTR)
#define GEMM_SMEM (3*3*GTILE*2)               // 92,160 B

template<int MODE>
__global__ void __launch_bounds__(256, 2) gemm_bf(const float* __restrict__ b0p,
                                                  const float* __restrict__ b1p,
                                                  const float* __restrict__ b2p,
                                                  float* __restrict__ Cout)
{
    extern __shared__ __align__(16) char gsm[];
    __half* Sm = (__half*)gsm;

    const int z = (MODE == 0) ? blockIdx.z : 3;
    const __half* gAh = (MODE == 4) ? g_ah : g_xh;
    const __half* gAl = (MODE == 4) ? g_al : g_xl;
    const __half* gB  = g_wt[z];
    const float* bias = (MODE == 4) ? b0p : (z == 0) ? b0p : (z == 1) ? b1p : b2p;

    const int bm = blockIdx.x * 128, bn = blockIdx.y * 128;
    const int t = threadIdx.x, lane = t & 31, w = t >> 5;
    const int wm = (w >> 2) * 64, wn = (w & 3) * 32;

    float acc[4][4][4];
    #pragma unroll
    for (int i = 0; i < 4; i++)
        #pragma unroll
        for (int j = 0; j < 4; j++)
            #pragma unroll
            for (int q = 0; q < 4; q++) acc[i][j][q] = 0.f;

    auto prefetch = [&](int kt, int stage) {
        const int k0 = kt * 32;
        __half* base = Sm + stage * 3 * GTILE;
        #pragma unroll
        for (int i = 0; i < 6; i++) {       // 3 tiles x 512 chunks = 1536
            const int c = t + i * 256;
            const int tile = c >> 9, cc = c & 511;
            const int row = cc >> 2, col = (cc & 3) * 8;
            const __half* g = (tile == 0) ? gAh : (tile == 1) ? gAl : gB;
            const int gr = ((tile < 2) ? bm : bn) + row;
            cp16(base + tile * GTILE + row * GSTR + col,
                 g + (size_t)gr * DMODEL + k0 + col);
        }
        CP_COMMIT();
    };

    prefetch(0, 0);
    prefetch(1, 1);

    const int laneA = (lane & 15) * GSTR + (lane >> 4) * 8;
    const int laneB = ((lane & 7) + ((lane >> 4) & 1) * 8) * GSTR + ((lane >> 3) & 1) * 8;

    int stage = 0;
    for (int kt = 0; kt < 24; kt++) {
        // group for kt completes when <=1 groups remain outstanding (kt, kt+1
        // in flight).  Last iteration has only its own group -> full drain.
        if (kt < 23) { CP_WAIT(1); } else { CP_WAIT(0); }
        __syncthreads();
        if (kt + 2 < 24) {
            int ps = stage + 2; if (ps >= 3) ps -= 3;
            prefetch(kt + 2, ps);
        }

        const __half* Ah = Sm + (stage * 3 + 0) * GTILE;
        const __half* Al = Sm + (stage * 3 + 1) * GTILE;
        const __half* Bs = Sm + (stage * 3 + 2) * GTILE;

        #pragma unroll
        for (int ks = 0; ks < 32; ks += 16) {
            uint32_t b_[2][4];
            #pragma unroll
            for (int p = 0; p < 2; p++) {
                const int off = (wn + p * 16) * GSTR + ks + laneB;
                ldsm_x4(b_[p][0], b_[p][1], b_[p][2], b_[p][3], sm_addr(Bs + off));
            }
            #pragma unroll
            for (int mt_ = 0; mt_ < 4; mt_++) {
                const int off = (wm + mt_ * 16) * GSTR + ks + laneA;
                uint32_t ah_[4], al_[4];
                ldsm_x4(ah_[0], ah_[1], ah_[2], ah_[3], sm_addr(Ah + off));
                ldsm_x4(al_[0], al_[1], al_[2], al_[3], sm_addr(Al + off));
                #pragma unroll
                for (int p = 0; p < 2; p++) {
                    mma16h(acc[mt_][2*p],   ah_, b_[p][0], b_[p][1]);
                    mma16h(acc[mt_][2*p],   al_, b_[p][0], b_[p][1]);
                    mma16h(acc[mt_][2*p+1], ah_, b_[p][2], b_[p][3]);
                    mma16h(acc[mt_][2*p+1], al_, b_[p][2], b_[p][3]);
                }
            }
        }
        if (++stage == 3) stage = 0;
    }

    // ---- epilogue ----
    #pragma unroll
    for (int mt_ = 0; mt_ < 4; mt_++) {
        #pragma unroll
        for (int nt = 0; nt < 4; nt++) {
            const int n0 = bn + wn + nt*8 + 2*(lane & 3);
            const float bb0 = bias[n0], bb1 = bias[n0+1];
            #pragma unroll
            for (int half_ = 0; half_ < 2; half_++) {
                const int r = bm + wm + mt_*16 + (lane >> 2) + half_*8;
                float c0 = acc[mt_][nt][half_*2+0] + bb0;
                float c1 = acc[mt_][nt][half_*2+1] + bb1;
                if (MODE == 4) {
                    *(float2*)&Cout[(size_t)r*DMODEL + n0] = make_float2(c0, c1);
                } else {
                    const int b_ = r >> 10, s = r & (SEQ-1);
                    const int h_ = n0 >> 6, d = n0 & 63;
                    const int bh_i = b_ * NHEAD + h_;
                    const size_t o = ((size_t)bh_i*SEQ + s)*HDIM + d;
                    if (z == 0) {          // Q: fp16 2-term, scaled
                        uint32_t Hu, Lu;
                        packsplit_h(c0 * QSC2, c1 * QSC2, Hu, Lu);
                        *(uint32_t*)&g_qh[o] = Hu;
                        *(uint32_t*)&g_ql[o] = Lu;
                    } else if (z == 1) {   // K: fp16 SINGLE, scaled
                        __half2 hv = __floats2half2_rn(c0 * QSC2, c1 * QSC2);
                        *(uint32_t*)&g_kh[o] = *reinterpret_cast<uint32_t*>(&hv);
                    } else {               // V: fp16 2-term
                        uint32_t Hu, Lu;
                        packsplit_h(c0, c1, Hu, Lu);
                        *(uint32_t*)&g_vh[o] = Hu;
                        *(uint32_t*)&g_vl[o] = Lu;
                    }
                }
            }
        }
    }
}

// ------------------------- flash attention v8 (unchanged from R14) -----------
#define ASTR 72
#define KVTILE (64*ASTR)
#define QTILE (128*ASTR)
#define ATTN_SMEM ((2*QTILE + 6*KVTILE)*2)    // 92,160 B

__global__ void __launch_bounds__(256, 2) attn_bf()
{
    extern __shared__ __align__(16) char smraw[];
    __half* Qh = (__half*)smraw;
    __half* Ql = Qh + QTILE;
    __half* KV = Ql + QTILE;                   // [2 stages][K, Vh, Vl]

    const int t = threadIdx.x, lane = t & 31, w = t >> 5;
    const int qt = blockIdx.x, bh = blockIdx.y;
    const int mt = w * 16;

    const size_t qoff = ((size_t)bh*SEQ + qt*128)*HDIM;
    const size_t koff = (size_t)bh*SEQ*HDIM;

    const int laneA = (lane & 15) * ASTR + (lane >> 4) * 8;
    const int laneB = ((lane & 7) + ((lane >> 4) & 1) * 8) * ASTR + ((lane >> 3) & 1) * 8;
    const int laneV = (lane & 15) * ASTR + (lane >> 4) * 8;   // trans: rows=keys

    // Q load
    #pragma unroll
    for (int i = 0; i < 8; i++) {
        const int c = t + i * 256;
        const int tile = c >> 10, cc = c & 1023;
        const int r = cc >> 3, col = (cc & 7) * 8;
        cp16((tile ? Ql : Qh) + r*ASTR + col,
             (tile ? g_ql : g_qh) + qoff + r*HDIM + col);
    }
    CP_COMMIT();

    auto prefetch = [&](int kt, int st) {
        __half* base = KV + st * 3 * KVTILE;
        #pragma unroll
        for (int i = 0; i < 6; i++) {
            const int c = t + i * 256;
            const int tile = c >> 9, cc = c & 511;
            const int r = cc >> 3, col = (cc & 7) * 8;
            const __half* g = (tile == 0) ? g_kh : (tile == 1) ? g_vh : g_vl;
            cp16(base + tile*KVTILE + r*ASTR + col,
                 g + koff + (size_t)(kt*64 + r)*HDIM + col);
        }
        CP_COMMIT();
    };

    prefetch(0, 0);

    float m0 = -1e30f, m1 = -1e30f, l0 = 0.f, l1 = 0.f;
    float o[8][4];
    #pragma unroll
    for (int i = 0; i < 8; i++)
        #pragma unroll
        for (int j = 0; j < 4; j++) o[i][j] = 0.f;

    for (int kt = 0; kt < SEQ/64; kt++) {
        const int st = kt & 1;
        CP_WAIT(0);
        __syncthreads();
        if (kt + 1 < SEQ/64) prefetch(kt + 1, st ^ 1);

        const __half* Ks = KV + (st*3 + 0)*KVTILE;
        const __half* Vh = KV + (st*3 + 1)*KVTILE;
        const __half* Vl = KV + (st*3 + 2)*KVTILE;

        // ---- S[16 x 64] = (Qh+Ql) K^T  (log2 units) ----
        float sc[8][4];
        #pragma unroll
        for (int i = 0; i < 8; i++)
            #pragma unroll
            for (int j = 0; j < 4; j++) sc[i][j] = 0.f;

        #pragma unroll
        for (int ks4 = 0; ks4 < 4; ks4++) {
            uint32_t qh_[4], ql_[4];
            const int qo = mt*ASTR + ks4*16 + laneA;
            ldsm_x4(qh_[0], qh_[1], qh_[2], qh_[3], sm_addr(Qh + qo));
            ldsm_x4(ql_[0], ql_[1], ql_[2], ql_[3], sm_addr(Ql + qo));
            #pragma unroll
            for (int p = 0; p < 4; p++) {
                uint32_t kk[4];
                const int off = (p*16)*ASTR + ks4*16 + laneB;
                ldsm_x4(kk[0], kk[1], kk[2], kk[3], sm_addr(Ks + off));
                mma16h(sc[2*p],   qh_, kk[0], kk[1]);
                mma16h(sc[2*p],   ql_, kk[0], kk[1]);
                mma16h(sc[2*p+1], qh_, kk[2], kk[3]);
                mma16h(sc[2*p+1], ql_, kk[2], kk[3]);
            }
        }

        // ---- warp-local online softmax (base-2, fp16 P via h2exp2) ----
        float mx0 = sc[0][0], mx1 = sc[0][2];
        #pragma unroll
        for (int nt = 0; nt < 8; nt++) {
            mx0 = fmaxf(mx0, fmaxf(sc[nt][0], sc[nt][1]));
            mx1 = fmaxf(mx1, fmaxf(sc[nt][2], sc[nt][3]));
        }
        mx0 = fmaxf(mx0, __shfl_xor_sync(0xffffffffu, mx0, 1));
        mx0 = fmaxf(mx0, __shfl_xor_sync(0xffffffffu, mx0, 2));
        mx1 = fmaxf(mx1, __shfl_xor_sync(0xffffffffu, mx1, 1));
        mx1 = fmaxf(mx1, __shfl_xor_sync(0xffffffffu, mx1, 2));
        const float mn0 = fmaxf(m0, mx0), mn1 = fmaxf(m1, mx1);
        const float cr0 = ex2(m0 - mn0), cr1 = ex2(m1 - mn1);
        m0 = mn0; m1 = mn1;

        uint32_t pa[8], pb[8];
        float s0 = 0.f, s1 = 0.f;
        #pragma unroll
        for (int nt = 0; nt < 8; nt++) {
            __half2 e0 = h2exp2(__floats2half2_rn(sc[nt][0] - mn0, sc[nt][1] - mn0));
            __half2 e1 = h2exp2(__floats2half2_rn(sc[nt][2] - mn1, sc[nt][3] - mn1));
            pa[nt] = *reinterpret_cast<uint32_t*>(&e0);
            pb[nt] = *reinterpret_cast<uint32_t*>(&e1);
            float2 f0 = __half22float2(e0), f1 = __half22float2(e1);
            s0 += f0.x + f0.y;
            s1 += f1.x + f1.y;
        }
        s0 += __shfl_xor_sync(0xffffffffu, s0, 1);
        s0 += __shfl_xor_sync(0xffffffffu, s0, 2);
        s1 += __shfl_xor_sync(0xffffffffu, s1, 1);
        s1 += __shfl_xor_sync(0xffffffffu, s1, 2);
        l0 = l0*cr0 + s0;
        l1 = l1*cr1 + s1;

        #pragma unroll
        for (int nt = 0; nt < 8; nt++) {
            o[nt][0] *= cr0; o[nt][1] *= cr0;
            o[nt][2] *= cr1; o[nt][3] *= cr1;
        }

        // ---- O += P V (fp16: P exact, V 2-term) ----
        #pragma unroll
        for (int c = 0; c < 4; c++) {
            const uint32_t ph_[4] = { pa[2*c], pb[2*c], pa[2*c+1], pb[2*c+1] };
            #pragma unroll
            for (int p = 0; p < 4; p++) {
                uint32_t vh_[4], vl_[4];
                const int off = (c*16)*ASTR + p*16 + laneV;
                ldsm_x4_t(vh_[0], vh_[1], vh_[2], vh_[3], sm_addr(Vh + off));
                ldsm_x4_t(vl_[0], vl_[1], vl_[2], vl_[3], sm_addr(Vl + off));
                mma16h(o[2*p],   ph_, vh_[0], vh_[1]);
                mma16h(o[2*p],   ph_, vl_[0], vl_[1]);
                mma16h(o[2*p+1], ph_, vh_[2], vh_[3]);
                mma16h(o[2*p+1], ph_, vl_[2], vl_[3]);
            }
        }
    }

    // ---- normalize + write fp16-split [B,S,D] for the O GEMM ----
    const int b_ = bh / NHEAD, h_ = bh % NHEAD;
    const int r0 = mt + (lane >> 2);
    const float inv0 = 1.f / l0, inv1 = 1.f / l1;
    const size_t row0 = (size_t)b_*SEQ + qt*128 + r0;
    #pragma unroll
    for (int nt = 0; nt < 8; nt++) {
        const int cc = nt*8 + 2*(lane & 3);
        uint32_t Hu, Lu;
        packsplit_h(o[nt][0]*inv0, o[nt][1]*inv0, Hu, Lu);
        *(uint32_t*)&g_ah[row0*DMODEL + h_*HDIM + cc] = Hu;
        *(uint32_t*)&g_al[row0*DMODEL + h_*HDIM + cc] = Lu;
        packsplit_h(o[nt][2]*inv1, o[nt][3]*inv1, Hu, Lu);
        *(uint32_t*)&g_ah[(row0 + 8)*DMODEL + h_*HDIM + cc] = Hu;
        *(uint32_t*)&g_al[(row0 + 8)*DMODEL + h_*HDIM + cc] = Lu;
    }
}

// ---------------------------------------------------------------------------
extern "C" void kernel_launch(void* const* d_in, const int* in_sizes, int n_in,
                              void* d_out, int out_size)
{
    (void)in_sizes; (void)n_in; (void)out_size;
    const float* x  = (const float*)d_in[0];
    const float* Wq = (const float*)d_in[1];
    const float* bq = (const float*)d_in[2];
    const float* Wk = (const float*)d_in[3];
    const float* bk = (const float*)d_in[4];
    const float* Wv = (const float*)d_in[5];
    const float* bv = (const float*)d_in[6];
    const float* Wo = (const float*)d_in[7];
    const float* bo = (const float*)d_in[8];
    float* out = (float*)d_out;

    prep_x<<<(MROWS*DMODEL/4)/256, 256>>>(x);
    prep_wt<<<dim3(DMODEL/32, DMODEL/32, 4), 256>>>(Wq, Wk, Wv, Wo);

    cudaFuncSetAttribute(gemm_bf<0>, cudaFuncAttributeMaxDynamicSharedMemorySize, GEMM_SMEM);
    cudaFuncSetAttribute(gemm_bf<4>, cudaFuncAttributeMaxDynamicSharedMemorySize, GEMM_SMEM);
    cudaFuncSetAttribute(attn_bf, cudaFuncAttributeMaxDynamicSharedMemorySize, ATTN_SMEM);

    dim3 gq(MROWS/128, DMODEL/128, 3);   // fused QKV
    gemm_bf<0><<<gq, 256, GEMM_SMEM>>>(bq, bk, bv, nullptr);

    attn_bf<<<dim3(SEQ/128, BATCH*NHEAD), 256, ATTN_SMEM>>>();

    dim3 gg(MROWS/128, DMODEL/128);
    gemm_bf<4><<<gg, 256, GEMM_SMEM>>>(bo, nullptr, nullptr, out);
}

// round 16
// speedup vs baseline: 1.1073x; 1.1073x over previous
#include <cuda_runtime.h>
#include <cuda_bf16.h>
#include <cuda_fp16.h>
#include <math.h>
#include <stdint.h>

#define BATCH 8
#define SEQ 1024
#define DMODEL 768
#define NHEAD 12
#define HDIM 64
#define MROWS (BATCH*SEQ)

// sqrt(1/sqrt(64) * log2(e)) — applied to BOTH Q and K so S lands in log2 domain
#define QSC2 0.42466089981329596f

// ------------------------- device scratch (no allocs) -----------------------
__device__ __align__(16) __half g_xh[MROWS*DMODEL];       // x fp16 split [M][K]
__device__ __align__(16) __half g_xl[MROWS*DMODEL];
__device__ __align__(16) __half g_wt[4][DMODEL*DMODEL];   // W^T single fp16 [N][K]
__device__ __align__(16) __half g_qh[MROWS*DMODEL];       // Q*QSC2 fp16 split
__device__ __align__(16) __half g_ql[MROWS*DMODEL];
__device__ __align__(16) __half g_kh[MROWS*DMODEL];       // K*QSC2 fp16 SINGLE
__device__ __align__(16) __half g_vh[MROWS*DMODEL];       // V fp16 SINGLE [bh][s][d]
__device__ __align__(16) __half g_ah[MROWS*DMODEL];       // attn out fp16 split [M][K]
__device__ __align__(16) __half g_al[MROWS*DMODEL];

// ------------------------- helpers ------------------------------------------
__device__ __forceinline__ void mma16h(float c[4], const uint32_t a[4],
                                       uint32_t b0, uint32_t b1) {
    asm volatile("mma.sync.aligned.m16n8k16.row.col.f32.f16.f16.f32 "
        "{%0,%1,%2,%3}, {%4,%5,%6,%7}, {%8,%9}, {%0,%1,%2,%3};"
        : "+f"(c[0]), "+f"(c[1]), "+f"(c[2]), "+f"(c[3])
        : "r"(a[0]), "r"(a[1]), "r"(a[2]), "r"(a[3]), "r"(b0), "r"(b1));
}
__device__ __forceinline__ uint32_t sm_addr(const void* p) {
    return (uint32_t)__cvta_generic_to_shared(p);
}
__device__ __forceinline__ void ldsm_x4(uint32_t& r0, uint32_t& r1, uint32_t& r2,
                                        uint32_t& r3, uint32_t addr) {
    asm volatile("ldmatrix.sync.aligned.m8n8.x4.shared.b16 {%0,%1,%2,%3}, [%4];"
        : "=r"(r0), "=r"(r1), "=r"(r2), "=r"(r3) : "r"(addr));
}
__device__ __forceinline__ void ldsm_x4_t(uint32_t& r0, uint32_t& r1, uint32_t& r2,
                                          uint32_t& r3, uint32_t addr) {
    asm volatile("ldmatrix.sync.aligned.m8n8.x4.trans.shared.b16 {%0,%1,%2,%3}, [%4];"
        : "=r"(r0), "=r"(r1), "=r"(r2), "=r"(r3) : "r"(addr));
}
__device__ __forceinline__ void cp16(void* dst, const void* src) {
    asm volatile("cp.async.cg.shared.global [%0], [%1], 16;"
        :: "r"(sm_addr(dst)), "l"(src));
}
#define CP_COMMIT() asm volatile("cp.async.commit_group;" ::: "memory")
#define CP_WAIT(n)  asm volatile("cp.async.wait_group %0;" :: "n"(n) : "memory")
__device__ __forceinline__ float ex2(float x) {
    float r; asm("ex2.approx.ftz.f32 %0, %1;" : "=f"(r) : "f"(x)); return r;
}
// fp16 round-split of two floats
__device__ __forceinline__ void packsplit_h(float x, float y, uint32_t& H, uint32_t& L) {
    __half2 h = __floats2half2_rn(x, y);
    float2 hf = __half22float2(h);
    __half2 l = __floats2half2_rn(x - hf.x, y - hf.y);
    H = *reinterpret_cast<uint32_t*>(&h);
    L = *reinterpret_cast<uint32_t*>(&l);
}

// ------------------------- prep kernels -------------------------------------
__global__ void __launch_bounds__(256) prep_x(const float* __restrict__ x)
{
    const int i = blockIdx.x * 256 + threadIdx.x;   // float4 index
    float4 v = ((const float4*)x)[i];
    uint32_t H0, L0, H1, L1;
    packsplit_h(v.x, v.y, H0, L0);
    packsplit_h(v.z, v.w, H1, L1);
    ((uint2*)g_xh)[i] = make_uint2(H0, H1);
    ((uint2*)g_xl)[i] = make_uint2(L0, L1);
}

__global__ void __launch_bounds__(256) prep_wt(const float* __restrict__ Wq,
                                               const float* __restrict__ Wk,
                                               const float* __restrict__ Wv,
                                               const float* __restrict__ Wo)
{
    __shared__ float tile[32][33];
    const int wid = blockIdx.z;
    const float* W = (wid == 0) ? Wq : (wid == 1) ? Wk : (wid == 2) ? Wv : Wo;
    const int n0 = blockIdx.x * 32, k0 = blockIdx.y * 32;
    const int tx = threadIdx.x & 31, ty = threadIdx.x >> 5;
    #pragma unroll
    for (int i = 0; i < 32; i += 8)
        tile[ty + i][tx] = W[(size_t)(k0 + ty + i) * DMODEL + n0 + tx];
    __syncthreads();
    #pragma unroll
    for (int i = 0; i < 32; i += 8)
        g_wt[wid][(size_t)(n0 + ty + i) * DMODEL + k0 + tx] =
            __float2half_rn(tile[tx][ty + i]);
}

// ------------------------- fp16 GEMM (R14 two-stage version) -----------------
// MODE 0: fused QKV (blockIdx.z)   MODE 4: O proj -> fp32 out
// C = (Ah + Al) * W^T;  2 MMAs per k16 block.
#define GSTR 40
#define GTILE (128*GSTR)
#define GEMM_SMEM (2*3*GTILE*2)               // 61,440 B

template<int MODE>
__global__ void __launch_bounds__(256, 2) gemm_bf(const float* __restrict__ b0p,
                                                  const float* __restrict__ b1p,
                                                  const float* __restrict__ b2p,
                                                  float* __restrict__ Cout)
{
    extern __shared__ __align__(16) char gsm[];
    __half* Sm = (__half*)gsm;

    const int z = (MODE == 0) ? blockIdx.z : 3;
    const __half* gAh = (MODE == 4) ? g_ah : g_xh;
    const __half* gAl = (MODE == 4) ? g_al : g_xl;
    const __half* gB  = g_wt[z];
    const float* bias = (MODE == 4) ? b0p : (z == 0) ? b0p : (z == 1) ? b1p : b2p;

    const int bm = blockIdx.x * 128, bn = blockIdx.y * 128;
    const int t = threadIdx.x, lane = t & 31, w = t >> 5;
    const int wm = (w >> 2) * 64, wn = (w & 3) * 32;

    float acc[4][4][4];
    #pragma unroll
    for (int i = 0; i < 4; i++)
        #pragma unroll
        for (int j = 0; j < 4; j++)
            #pragma unroll
            for (int q = 0; q < 4; q++) acc[i][j][q] = 0.f;

    auto prefetch = [&](int kt, int stage) {
        const int k0 = kt * 32;
        __half* base = Sm + stage * 3 * GTILE;
        #pragma unroll
        for (int i = 0; i < 6; i++) {       // 3 tiles x 512 chunks = 1536
            const int c = t + i * 256;
            const int tile = c >> 9, cc = c & 511;
            const int row = cc >> 2, col = (cc & 3) * 8;
            const __half* g = (tile == 0) ? gAh : (tile == 1) ? gAl : gB;
            const int gr = ((tile < 2) ? bm : bn) + row;
            cp16(base + tile * GTILE + row * GSTR + col,
                 g + (size_t)gr * DMODEL + k0 + col);
        }
        CP_COMMIT();
    };

    prefetch(0, 0);

    const int laneA = (lane & 15) * GSTR + (lane >> 4) * 8;
    const int laneB = ((lane & 7) + ((lane >> 4) & 1) * 8) * GSTR + ((lane >> 3) & 1) * 8;

    for (int kt = 0; kt < 24; kt++) {
        const int stage = kt & 1;
        CP_WAIT(0);
        __syncthreads();
        if (kt + 1 < 24) prefetch(kt + 1, stage ^ 1);

        const __half* Ah = Sm + (stage * 3 + 0) * GTILE;
        const __half* Al = Sm + (stage * 3 + 1) * GTILE;
        const __half* Bs = Sm + (stage * 3 + 2) * GTILE;

        #pragma unroll
        for (int ks = 0; ks < 32; ks += 16) {
            uint32_t b_[2][4];
            #pragma unroll
            for (int p = 0; p < 2; p++) {
                const int off = (wn + p * 16) * GSTR + ks + laneB;
                ldsm_x4(b_[p][0], b_[p][1], b_[p][2], b_[p][3], sm_addr(Bs + off));
            }
            #pragma unroll
            for (int mt_ = 0; mt_ < 4; mt_++) {
                const int off = (wm + mt_ * 16) * GSTR + ks + laneA;
                uint32_t ah_[4], al_[4];
                ldsm_x4(ah_[0], ah_[1], ah_[2], ah_[3], sm_addr(Ah + off));
                ldsm_x4(al_[0], al_[1], al_[2], al_[3], sm_addr(Al + off));
                #pragma unroll
                for (int p = 0; p < 2; p++) {
                    mma16h(acc[mt_][2*p],   ah_, b_[p][0], b_[p][1]);
                    mma16h(acc[mt_][2*p],   al_, b_[p][0], b_[p][1]);
                    mma16h(acc[mt_][2*p+1], ah_, b_[p][2], b_[p][3]);
                    mma16h(acc[mt_][2*p+1], al_, b_[p][2], b_[p][3]);
                }
            }
        }
    }

    // ---- epilogue ----
    #pragma unroll
    for (int mt_ = 0; mt_ < 4; mt_++) {
        #pragma unroll
        for (int nt = 0; nt < 4; nt++) {
            const int n0 = bn + wn + nt*8 + 2*(lane & 3);
            const float bb0 = bias[n0], bb1 = bias[n0+1];
            #pragma unroll
            for (int half_ = 0; half_ < 2; half_++) {
                const int r = bm + wm + mt_*16 + (lane >> 2) + half_*8;
                float c0 = acc[mt_][nt][half_*2+0] + bb0;
                float c1 = acc[mt_][nt][half_*2+1] + bb1;
                if (MODE == 4) {
                    *(float2*)&Cout[(size_t)r*DMODEL + n0] = make_float2(c0, c1);
                } else {
                    const int b_ = r >> 10, s = r & (SEQ-1);
                    const int h_ = n0 >> 6, d = n0 & 63;
                    const int bh_i = b_ * NHEAD + h_;
                    const size_t o = ((size_t)bh_i*SEQ + s)*HDIM + d;
                    if (z == 0) {          // Q: fp16 2-term, scaled
                        uint32_t Hu, Lu;
                        packsplit_h(c0 * QSC2, c1 * QSC2, Hu, Lu);
                        *(uint32_t*)&g_qh[o] = Hu;
                        *(uint32_t*)&g_ql[o] = Lu;
                    } else if (z == 1) {   // K: fp16 SINGLE, scaled
                        __half2 hv = __floats2half2_rn(c0 * QSC2, c1 * QSC2);
                        *(uint32_t*)&g_kh[o] = *reinterpret_cast<uint32_t*>(&hv);
                    } else {               // V: fp16 SINGLE
                        __half2 hv = __floats2half2_rn(c0, c1);
                        *(uint32_t*)&g_vh[o] = *reinterpret_cast<uint32_t*>(&hv);
                    }
                }
            }
        }
    }
}

// ------------------------- flash attention v9 --------------------------------
// 128-q tile, 8 warps; warp w owns q rows [w*16, w*16+16) over ALL 64 keys.
// fp16 everywhere: S = (Qh+Ql)·K (K single), exact fp16 P via h2exp2,
// PV = P·V (V single).  KV: 2 tiles/stage, double-buffered.
#define ASTR 72
#define KVTILE (64*ASTR)
#define QTILE (128*ASTR)
#define ATTN_SMEM ((2*QTILE + 4*KVTILE)*2)    // 73,728 B

__global__ void __launch_bounds__(256, 2) attn_bf()
{
    extern __shared__ __align__(16) char smraw[];
    __half* Qh = (__half*)smraw;
    __half* Ql = Qh + QTILE;
    __half* KV = Ql + QTILE;                   // [2 stages][K, V]

    const int t = threadIdx.x, lane = t & 31, w = t >> 5;
    const int qt = blockIdx.x, bh = blockIdx.y;
    const int mt = w * 16;

    const size_t qoff = ((size_t)bh*SEQ + qt*128)*HDIM;
    const size_t koff = (size_t)bh*SEQ*HDIM;

    const int laneA = (lane & 15) * ASTR + (lane >> 4) * 8;
    const int laneB = ((lane & 7) + ((lane >> 4) & 1) * 8) * ASTR + ((lane >> 3) & 1) * 8;
    const int laneV = (lane & 15) * ASTR + (lane >> 4) * 8;   // trans: rows=keys

    // Q load
    #pragma unroll
    for (int i = 0; i < 8; i++) {
        const int c = t + i * 256;
        const int tile = c >> 10, cc = c & 1023;
        const int r = cc >> 3, col = (cc & 7) * 8;
        cp16((tile ? Ql : Qh) + r*ASTR + col,
             (tile ? g_ql : g_qh) + qoff + r*HDIM + col);
    }
    CP_COMMIT();

    auto prefetch = [&](int kt, int st) {
        __half* base = KV + st * 2 * KVTILE;
        #pragma unroll
        for (int i = 0; i < 4; i++) {       // 2 tiles x 512 chunks = 1024
            const int c = t + i * 256;
            const int tile = c >> 9, cc = c & 511;
            const int r = cc >> 3, col = (cc & 7) * 8;
            const __half* g = (tile == 0) ? g_kh : g_vh;
            cp16(base + tile*KVTILE + r*ASTR + col,
                 g + koff + (size_t)(kt*64 + r)*HDIM + col);
        }
        CP_COMMIT();
    };

    prefetch(0, 0);

    float m0 = -1e30f, m1 = -1e30f, l0 = 0.f, l1 = 0.f;
    float o[8][4];
    #pragma unroll
    for (int i = 0; i < 8; i++)
        #pragma unroll
        for (int j = 0; j < 4; j++) o[i][j] = 0.f;

    for (int kt = 0; kt < SEQ/64; kt++) {
        const int st = kt & 1;
        CP_WAIT(0);
        __syncthreads();
        if (kt + 1 < SEQ/64) prefetch(kt + 1, st ^ 1);

        const __half* Ks = KV + (st*2 + 0)*KVTILE;
        const __half* Vs = KV + (st*2 + 1)*KVTILE;

        // ---- S[16 x 64] = (Qh+Ql) K^T  (log2 units) ----
        float sc[8][4];
        #pragma unroll
        for (int i = 0; i < 8; i++)
            #pragma unroll
            for (int j = 0; j < 4; j++) sc[i][j] = 0.f;

        #pragma unroll
        for (int ks4 = 0; ks4 < 4; ks4++) {
            uint32_t qh_[4], ql_[4];
            const int qo = mt*ASTR + ks4*16 + laneA;
            ldsm_x4(qh_[0], qh_[1], qh_[2], qh_[3], sm_addr(Qh + qo));
            ldsm_x4(ql_[0], ql_[1], ql_[2], ql_[3], sm_addr(Ql + qo));
            #pragma unroll
            for (int p = 0; p < 4; p++) {
                uint32_t kk[4];
                const int off = (p*16)*ASTR + ks4*16 + laneB;
                ldsm_x4(kk[0], kk[1], kk[2], kk[3], sm_addr(Ks + off));
                mma16h(sc[2*p],   qh_, kk[0], kk[1]);
                mma16h(sc[2*p],   ql_, kk[0], kk[1]);
                mma16h(sc[2*p+1], qh_, kk[2], kk[3]);
                mma16h(sc[2*p+1], ql_, kk[2], kk[3]);
            }
        }

        // ---- warp-local online softmax (base-2, fp16 P via h2exp2) ----
        float mx0 = sc[0][0], mx1 = sc[0][2];
        #pragma unroll
        for (int nt = 0; nt < 8; nt++) {
            mx0 = fmaxf(mx0, fmaxf(sc[nt][0], sc[nt][1]));
            mx1 = fmaxf(mx1, fmaxf(sc[nt][2], sc[nt][3]));
        }
        mx0 = fmaxf(mx0, __shfl_xor_sync(0xffffffffu, mx0, 1));
        mx0 = fmaxf(mx0, __shfl_xor_sync(0xffffffffu, mx0, 2));
        mx1 = fmaxf(mx1, __shfl_xor_sync(0xffffffffu, mx1, 1));
        mx1 = fmaxf(mx1, __shfl_xor_sync(0xffffffffu, mx1, 2));
        const float mn0 = fmaxf(m0, mx0), mn1 = fmaxf(m1, mx1);
        const float cr0 = ex2(m0 - mn0), cr1 = ex2(m1 - mn1);
        m0 = mn0; m1 = mn1;

        uint32_t pa[8], pb[8];
        float s0 = 0.f, s1 = 0.f;
        #pragma unroll
        for (int nt = 0; nt < 8; nt++) {
            __half2 e0 = h2exp2(__floats2half2_rn(sc[nt][0] - mn0, sc[nt][1] - mn0));
            __half2 e1 = h2exp2(__floats2half2_rn(sc[nt][2] - mn1, sc[nt][3] - mn1));
            pa[nt] = *reinterpret_cast<uint32_t*>(&e0);
            pb[nt] = *reinterpret_cast<uint32_t*>(&e1);
            float2 f0 = __half22float2(e0), f1 = __half22float2(e1);
            s0 += f0.x + f0.y;
            s1 += f1.x + f1.y;
        }
        s0 += __shfl_xor_sync(0xffffffffu, s0, 1);
        s0 += __shfl_xor_sync(0xffffffffu, s0, 2);
        s1 += __shfl_xor_sync(0xffffffffu, s1, 1);
        s1 += __shfl_xor_sync(0xffffffffu, s1, 2);
        l0 = l0*cr0 + s0;
        l1 = l1*cr1 + s1;

        #pragma unroll
        for (int nt = 0; nt < 8; nt++) {
            o[nt][0] *= cr0; o[nt][1] *= cr0;
            o[nt][2] *= cr1; o[nt][3] *= cr1;
        }

        // ---- O += P V (fp16: P exact, V single) ----
        #pragma unroll
        for (int c = 0; c < 4; c++) {
            const uint32_t ph_[4] = { pa[2*c], pb[2*c], pa[2*c+1], pb[2*c+1] };
            #pragma unroll
            for (int p = 0; p < 4; p++) {
                uint32_t vv[4];
                const int off = (c*16)*ASTR + p*16 + laneV;
                ldsm_x4_t(vv[0], vv[1], vv[2], vv[3], sm_addr(Vs + off));
                mma16h(o[2*p],   ph_, vv[0], vv[1]);
                mma16h(o[2*p+1], ph_, vv[2], vv[3]);
            }
        }
    }

    // ---- normalize + write fp16-split [B,S,D] for the O GEMM ----
    const int b_ = bh / NHEAD, h_ = bh % NHEAD;
    const int r0 = mt + (lane >> 2);
    const float inv0 = 1.f / l0, inv1 = 1.f / l1;
    const size_t row0 = (size_t)b_*SEQ + qt*128 + r0;
    #pragma unroll
    for (int nt = 0; nt < 8; nt++) {
        const int cc = nt*8 + 2*(lane & 3);
        uint32_t Hu, Lu;
        packsplit_h(o[nt][0]*inv0, o[nt][1]*inv0, Hu, Lu);
        *(uint32_t*)&g_ah[row0*DMODEL + h_*HDIM + cc] = Hu;
        *(uint32_t*)&g_al[row0*DMODEL + h_*HDIM + cc] = Lu;
        packsplit_h(o[nt][2]*inv1, o[nt][3]*inv1, Hu, Lu);
        *(uint32_t*)&g_ah[(row0 + 8)*DMODEL + h_*HDIM + cc] = Hu;
        *(uint32_t*)&g_al[(row0 + 8)*DMODEL + h_*HDIM + cc] = Lu;
    }
}

// ---------------------------------------------------------------------------
extern "C" void kernel_launch(void* const* d_in, const int* in_sizes, int n_in,
                              void* d_out, int out_size)
{
    (void)in_sizes; (void)n_in; (void)out_size;
    const float* x  = (const float*)d_in[0];
    const float* Wq = (const float*)d_in[1];
    const float* bq = (const float*)d_in[2];
    const float* Wk = (const float*)d_in[3];
    const float* bk = (const float*)d_in[4];
    const float* Wv = (const float*)d_in[5];
    const float* bv = (const float*)d_in[6];
    const float* Wo = (const float*)d_in[7];
    const float* bo = (const float*)d_in[8];
    float* out = (float*)d_out;

    prep_x<<<(MROWS*DMODEL/4)/256, 256>>>(x);
    prep_wt<<<dim3(DMODEL/32, DMODEL/32, 4), 256>>>(Wq, Wk, Wv, Wo);

    cudaFuncSetAttribute(gemm_bf<0>, cudaFuncAttributeMaxDynamicSharedMemorySize, GEMM_SMEM);
    cudaFuncSetAttribute(gemm_bf<4>, cudaFuncAttributeMaxDynamicSharedMemorySize, GEMM_SMEM);
    cudaFuncSetAttribute(attn_bf, cudaFuncAttributeMaxDynamicSharedMemorySize, ATTN_SMEM);

    dim3 gq(MROWS/128, DMODEL/128, 3);   // fused QKV
    gemm_bf<0><<<gq, 256, GEMM_SMEM>>>(bq, bk, bv, nullptr);

    attn_bf<<<dim3(SEQ/128, BATCH*NHEAD), 256, ATTN_SMEM>>>();

    dim3 gg(MROWS/128, DMODEL/128);
    gemm_bf<4><<<gg, 256, GEMM_SMEM>>>(bo, nullptr, nullptr, out);
}

// round 17
// speedup vs baseline: 1.4706x; 1.3280x over previous
#include <cuda_runtime.h>
#include <cuda_bf16.h>
#include <cuda_fp16.h>
#include <math.h>
#include <stdint.h>

#define BATCH 8
#define SEQ 1024
#define DMODEL 768
#define NHEAD 12
#define HDIM 64
#define MROWS (BATCH*SEQ)

// sqrt(1/sqrt(64) * log2(e)) — applied to BOTH Q and K so S lands in log2 domain
#define QSC2 0.42466089981329596f

// ------------------------- device scratch (no allocs) -----------------------
__device__ __align__(16) __half g_x [MROWS*DMODEL];       // x fp16 SINGLE [M][K]
__device__ __align__(16) __half g_wt[4][DMODEL*DMODEL];   // W^T single fp16 [N][K]
__device__ __align__(16) __half g_qh[MROWS*DMODEL];       // Q*QSC2 fp16 split
__device__ __align__(16) __half g_ql[MROWS*DMODEL];
__device__ __align__(16) __half g_kh[MROWS*DMODEL];       // K*QSC2 fp16 SINGLE
__device__ __align__(16) __half g_vh[MROWS*DMODEL];       // V fp16 SINGLE [bh][s][d]
__device__ __align__(16) __half g_a [MROWS*DMODEL];       // attn out fp16 SINGLE [M][K]

// ------------------------- helpers ------------------------------------------
__device__ __forceinline__ void mma16h(float c[4], const uint32_t a[4],
                                       uint32_t b0, uint32_t b1) {
    asm volatile("mma.sync.aligned.m16n8k16.row.col.f32.f16.f16.f32 "
        "{%0,%1,%2,%3}, {%4,%5,%6,%7}, {%8,%9}, {%0,%1,%2,%3};"
        : "+f"(c[0]), "+f"(c[1]), "+f"(c[2]), "+f"(c[3])
        : "r"(a[0]), "r"(a[1]), "r"(a[2]), "r"(a[3]), "r"(b0), "r"(b1));
}
__device__ __forceinline__ uint32_t sm_addr(const void* p) {
    return (uint32_t)__cvta_generic_to_shared(p);
}
__device__ __forceinline__ void ldsm_x4(uint32_t& r0, uint32_t& r1, uint32_t& r2,
                                        uint32_t& r3, uint32_t addr) {
    asm volatile("ldmatrix.sync.aligned.m8n8.x4.shared.b16 {%0,%1,%2,%3}, [%4];"
        : "=r"(r0), "=r"(r1), "=r"(r2), "=r"(r3) : "r"(addr));
}
__device__ __forceinline__ void ldsm_x4_t(uint32_t& r0, uint32_t& r1, uint32_t& r2,
                                          uint32_t& r3, uint32_t addr) {
    asm volatile("ldmatrix.sync.aligned.m8n8.x4.trans.shared.b16 {%0,%1,%2,%3}, [%4];"
        : "=r"(r0), "=r"(r1), "=r"(r2), "=r"(r3) : "r"(addr));
}
__device__ __forceinline__ void cp16(void* dst, const void* src) {
    asm volatile("cp.async.cg.shared.global [%0], [%1], 16;"
        :: "r"(sm_addr(dst)), "l"(src));
}
#define CP_COMMIT() asm volatile("cp.async.commit_group;" ::: "memory")
#define CP_WAIT(n)  asm volatile("cp.async.wait_group %0;" :: "n"(n) : "memory")
__device__ __forceinline__ float ex2(float x) {
    float r; asm("ex2.approx.ftz.f32 %0, %1;" : "=f"(r) : "f"(x)); return r;
}
// fp16 round-split of two floats
__device__ __forceinline__ void packsplit_h(float x, float y, uint32_t& H, uint32_t& L) {
    __half2 h = __floats2half2_rn(x, y);
    float2 hf = __half22float2(h);
    __half2 l = __floats2half2_rn(x - hf.x, y - hf.y);
    H = *reinterpret_cast<uint32_t*>(&h);
    L = *reinterpret_cast<uint32_t*>(&l);
}
__device__ __forceinline__ uint32_t packh(float x, float y) {
    __half2 h = __floats2half2_rn(x, y);
    return *reinterpret_cast<uint32_t*>(&h);
}

// ------------------------- prep kernels -------------------------------------
__global__ void __launch_bounds__(256) prep_x(const float* __restrict__ x)
{
    const int i = blockIdx.x * 256 + threadIdx.x;   // float4 index
    float4 v = ((const float4*)x)[i];
    ((uint2*)g_x)[i] = make_uint2(packh(v.x, v.y), packh(v.z, v.w));
}

__global__ void __launch_bounds__(256) prep_wt(const float* __restrict__ Wq,
                                               const float* __restrict__ Wk,
                                               const float* __restrict__ Wv,
                                               const float* __restrict__ Wo)
{
    __shared__ float tile[32][33];
    const int wid = blockIdx.z;
    const float* W = (wid == 0) ? Wq : (wid == 1) ? Wk : (wid == 2) ? Wv : Wo;
    const int n0 = blockIdx.x * 32, k0 = blockIdx.y * 32;
    const int tx = threadIdx.x & 31, ty = threadIdx.x >> 5;
    #pragma unroll
    for (int i = 0; i < 32; i += 8)
        tile[ty + i][tx] = W[(size_t)(k0 + ty + i) * DMODEL + n0 + tx];
    __syncthreads();
    #pragma unroll
    for (int i = 0; i < 32; i += 8)
        g_wt[wid][(size_t)(n0 + ty + i) * DMODEL + k0 + tx] =
            __float2half_rn(tile[tx][ty + i]);
}

// ------------------------- fp16 GEMM: A single x W single --------------------
// MODE 0: fused QKV (blockIdx.z)   MODE 4: O proj -> fp32 out
// C = A * W^T;  1 MMA per k16 per n8-pair.
#define GSTR 40
#define GTILE (128*GSTR)
#define GEMM_SMEM (2*2*GTILE*2)               // 40,960 B

template<int MODE>
__global__ void __launch_bounds__(256, 2) gemm_bf(const float* __restrict__ b0p,
                                                  const float* __restrict__ b1p,
                                                  const float* __restrict__ b2p,
                                                  float* __restrict__ Cout)
{
    extern __shared__ __align__(16) char gsm[];
    __half* Sm = (__half*)gsm;

    const int z = (MODE == 0) ? blockIdx.z : 3;
    const __half* gA = (MODE == 4) ? g_a : g_x;
    const __half* gB = g_wt[z];
    const float* bias = (MODE == 4) ? b0p : (z == 0) ? b0p : (z == 1) ? b1p : b2p;

    const int bm = blockIdx.x * 128, bn = blockIdx.y * 128;
    const int t = threadIdx.x, lane = t & 31, w = t >> 5;
    const int wm = (w >> 2) * 64, wn = (w & 3) * 32;

    float acc[4][4][4];
    #pragma unroll
    for (int i = 0; i < 4; i++)
        #pragma unroll
        for (int j = 0; j < 4; j++)
            #pragma unroll
            for (int q = 0; q < 4; q++) acc[i][j][q] = 0.f;

    auto prefetch = [&](int kt, int stage) {
        const int k0 = kt * 32;
        __half* base = Sm + stage * 2 * GTILE;
        #pragma unroll
        for (int i = 0; i < 4; i++) {       // 2 tiles x 512 chunks = 1024
            const int c = t + i * 256;
            const int tile = c >> 9, cc = c & 511;
            const int row = cc >> 2, col = (cc & 3) * 8;
            const __half* g = (tile == 0) ? gA : gB;
            const int gr = ((tile == 0) ? bm : bn) + row;
            cp16(base + tile * GTILE + row * GSTR + col,
                 g + (size_t)gr * DMODEL + k0 + col);
        }
        CP_COMMIT();
    };

    prefetch(0, 0);

    const int laneA = (lane & 15) * GSTR + (lane >> 4) * 8;
    const int laneB = ((lane & 7) + ((lane >> 4) & 1) * 8) * GSTR + ((lane >> 3) & 1) * 8;

    for (int kt = 0; kt < 24; kt++) {
        const int stage = kt & 1;
        CP_WAIT(0);
        __syncthreads();
        if (kt + 1 < 24) prefetch(kt + 1, stage ^ 1);

        const __half* As = Sm + (stage * 2 + 0) * GTILE;
        const __half* Bs = Sm + (stage * 2 + 1) * GTILE;

        #pragma unroll
        for (int ks = 0; ks < 32; ks += 16) {
            uint32_t b_[2][4];
            #pragma unroll
            for (int p = 0; p < 2; p++) {
                const int off = (wn + p * 16) * GSTR + ks + laneB;
                ldsm_x4(b_[p][0], b_[p][1], b_[p][2], b_[p][3], sm_addr(Bs + off));
            }
            #pragma unroll
            for (int mt_ = 0; mt_ < 4; mt_++) {
                const int off = (wm + mt_ * 16) * GSTR + ks + laneA;
                uint32_t a_[4];
                ldsm_x4(a_[0], a_[1], a_[2], a_[3], sm_addr(As + off));
                #pragma unroll
                for (int p = 0; p < 2; p++) {
                    mma16h(acc[mt_][2*p],   a_, b_[p][0], b_[p][1]);
                    mma16h(acc[mt_][2*p+1], a_, b_[p][2], b_[p][3]);
                }
            }
        }
    }

    // ---- epilogue ----
    #pragma unroll
    for (int mt_ = 0; mt_ < 4; mt_++) {
        #pragma unroll
        for (int nt = 0; nt < 4; nt++) {
            const int n0 = bn + wn + nt*8 + 2*(lane & 3);
            const float bb0 = bias[n0], bb1 = bias[n0+1];
            #pragma unroll
            for (int half_ = 0; half_ < 2; half_++) {
                const int r = bm + wm + mt_*16 + (lane >> 2) + half_*8;
                float c0 = acc[mt_][nt][half_*2+0] + bb0;
                float c1 = acc[mt_][nt][half_*2+1] + bb1;
                if (MODE == 4) {
                    *(float2*)&Cout[(size_t)r*DMODEL + n0] = make_float2(c0, c1);
                } else {
                    const int b_ = r >> 10, s = r & (SEQ-1);
                    const int h_ = n0 >> 6, d = n0 & 63;
                    const int bh_i = b_ * NHEAD + h_;
                    const size_t o = ((size_t)bh_i*SEQ + s)*HDIM + d;
                    if (z == 0) {          // Q: fp16 2-term, scaled
                        uint32_t Hu, Lu;
                        packsplit_h(c0 * QSC2, c1 * QSC2, Hu, Lu);
                        *(uint32_t*)&g_qh[o] = Hu;
                        *(uint32_t*)&g_ql[o] = Lu;
                    } else if (z == 1) {   // K: fp16 SINGLE, scaled
                        *(uint32_t*)&g_kh[o] = packh(c0 * QSC2, c1 * QSC2);
                    } else {               // V: fp16 SINGLE
                        *(uint32_t*)&g_vh[o] = packh(c0, c1);
                    }
                }
            }
        }
    }
}

// ------------------------- flash attention v9 (unchanged core) ---------------
// 128-q tile, 8 warps; warp w owns q rows [w*16, w*16+16) over ALL 64 keys.
// fp16 everywhere: S = (Qh+Ql)·K (K single), exact fp16 P via h2exp2,
// PV = P·V (V single).  KV: 2 tiles/stage, double-buffered.
#define ASTR 72
#define KVTILE (64*ASTR)
#define QTILE (128*ASTR)
#define ATTN_SMEM ((2*QTILE + 4*KVTILE)*2)    // 73,728 B

__global__ void __launch_bounds__(256, 2) attn_bf()
{
    extern __shared__ __align__(16) char smraw[];
    __half* Qh = (__half*)smraw;
    __half* Ql = Qh + QTILE;
    __half* KV = Ql + QTILE;                   // [2 stages][K, V]

    const int t = threadIdx.x, lane = t & 31, w = t >> 5;
    const int qt = blockIdx.x, bh = blockIdx.y;
    const int mt = w * 16;

    const size_t qoff = ((size_t)bh*SEQ + qt*128)*HDIM;
    const size_t koff = (size_t)bh*SEQ*HDIM;

    const int laneA = (lane & 15) * ASTR + (lane >> 4) * 8;
    const int laneB = ((lane & 7) + ((lane >> 4) & 1) * 8) * ASTR + ((lane >> 3) & 1) * 8;
    const int laneV = (lane & 15) * ASTR + (lane >> 4) * 8;   // trans: rows=keys

    // Q load
    #pragma unroll
    for (int i = 0; i < 8; i++) {
        const int c = t + i * 256;
        const int tile = c >> 10, cc = c & 1023;
        const int r = cc >> 3, col = (cc & 7) * 8;
        cp16((tile ? Ql : Qh) + r*ASTR + col,
             (tile ? g_ql : g_qh) + qoff + r*HDIM + col);
    }
    CP_COMMIT();

    auto prefetch = [&](int kt, int st) {
        __half* base = KV + st * 2 * KVTILE;
        #pragma unroll
        for (int i = 0; i < 4; i++) {       // 2 tiles x 512 chunks = 1024
            const int c = t + i * 256;
            const int tile = c >> 9, cc = c & 511;
            const int r = cc >> 3, col = (cc & 7) * 8;
            const __half* g = (tile == 0) ? g_kh : g_vh;
            cp16(base + tile*KVTILE + r*ASTR + col,
                 g + koff + (size_t)(kt*64 + r)*HDIM + col);
        }
        CP_COMMIT();
    };

    prefetch(0, 0);

    float m0 = -1e30f, m1 = -1e30f, l0 = 0.f, l1 = 0.f;
    float o[8][4];
    #pragma unroll
    for (int i = 0; i < 8; i++)
        #pragma unroll
        for (int j = 0; j < 4; j++) o[i][j] = 0.f;

    for (int kt = 0; kt < SEQ/64; kt++) {
        const int st = kt & 1;
        CP_WAIT(0);
        __syncthreads();
        if (kt + 1 < SEQ/64) prefetch(kt + 1, st ^ 1);

        const __half* Ks = KV + (st*2 + 0)*KVTILE;
        const __half* Vs = KV + (st*2 + 1)*KVTILE;

        // ---- S[16 x 64] = (Qh+Ql) K^T  (log2 units) ----
        float sc[8][4];
        #pragma unroll
        for (int i = 0; i < 8; i++)
            #pragma unroll
            for (int j = 0; j < 4; j++) sc[i][j] = 0.f;

        #pragma unroll
        for (int ks4 = 0; ks4 < 4; ks4++) {
            uint32_t qh_[4], ql_[4];
            const int qo = mt*ASTR + ks4*16 + laneA;
            ldsm_x4(qh_[0], qh_[1], qh_[2], qh_[3], sm_addr(Qh + qo));
            ldsm_x4(ql_[0], ql_[1], ql_[2], ql_[3], sm_addr(Ql + qo));
            #pragma unroll
            for (int p = 0; p < 4; p++) {
                uint32_t kk[4];
                const int off = (p*16)*ASTR + ks4*16 + laneB;
                ldsm_x4(kk[0], kk[1], kk[2], kk[3], sm_addr(Ks + off));
                mma16h(sc[2*p],   qh_, kk[0], kk[1]);
                mma16h(sc[2*p],   ql_, kk[0], kk[1]);
                mma16h(sc[2*p+1], qh_, kk[2], kk[3]);
                mma16h(sc[2*p+1], ql_, kk[2], kk[3]);
            }
        }

        // ---- warp-local online softmax (base-2, fp16 P via h2exp2) ----
        float mx0 = sc[0][0], mx1 = sc[0][2];
        #pragma unroll
        for (int nt = 0; nt < 8; nt++) {
            mx0 = fmaxf(mx0, fmaxf(sc[nt][0], sc[nt][1]));
            mx1 = fmaxf(mx1, fmaxf(sc[nt][2], sc[nt][3]));
        }
        mx0 = fmaxf(mx0, __shfl_xor_sync(0xffffffffu, mx0, 1));
        mx0 = fmaxf(mx0, __shfl_xor_sync(0xffffffffu, mx0, 2));
        mx1 = fmaxf(mx1, __shfl_xor_sync(0xffffffffu, mx1, 1));
        mx1 = fmaxf(mx1, __shfl_xor_sync(0xffffffffu, mx1, 2));
        const float mn0 = fmaxf(m0, mx0), mn1 = fmaxf(m1, mx1);
        const float cr0 = ex2(m0 - mn0), cr1 = ex2(m1 - mn1);
        m0 = mn0; m1 = mn1;

        uint32_t pa[8], pb[8];
        float s0 = 0.f, s1 = 0.f;
        #pragma unroll
        for (int nt = 0; nt < 8; nt++) {
            __half2 e0 = h2exp2(__floats2half2_rn(sc[nt][0] - mn0, sc[nt][1] - mn0));
            __half2 e1 = h2exp2(__floats2half2_rn(sc[nt][2] - mn1, sc[nt][3] - mn1));
            pa[nt] = *reinterpret_cast<uint32_t*>(&e0);
            pb[nt] = *reinterpret_cast<uint32_t*>(&e1);
            float2 f0 = __half22float2(e0), f1 = __half22float2(e1);
            s0 += f0.x + f0.y;
            s1 += f1.x + f1.y;
        }
        s0 += __shfl_xor_sync(0xffffffffu, s0, 1);
        s0 += __shfl_xor_sync(0xffffffffu, s0, 2);
        s1 += __shfl_xor_sync(0xffffffffu, s1, 1);
        s1 += __shfl_xor_sync(0xffffffffu, s1, 2);
        l0 = l0*cr0 + s0;
        l1 = l1*cr1 + s1;

        #pragma unroll
        for (int nt = 0; nt < 8; nt++) {
            o[nt][0] *= cr0; o[nt][1] *= cr0;
            o[nt][2] *= cr1; o[nt][3] *= cr1;
        }

        // ---- O += P V (fp16: P exact, V single) ----
        #pragma unroll
        for (int c = 0; c < 4; c++) {
            const uint32_t ph_[4] = { pa[2*c], pb[2*c], pa[2*c+1], pb[2*c+1] };
            #pragma unroll
            for (int p = 0; p < 4; p++) {
                uint32_t vv[4];
                const int off = (c*16)*ASTR + p*16 + laneV;
                ldsm_x4_t(vv[0], vv[1], vv[2], vv[3], sm_addr(Vs + off));
                mma16h(o[2*p],   ph_, vv[0], vv[1]);
                mma16h(o[2*p+1], ph_, vv[2], vv[3]);
            }
        }
    }

    // ---- normalize + write single-fp16 [B,S,D] for the O GEMM ----
    const int b_ = bh / NHEAD, h_ = bh % NHEAD;
    const int r0 = mt + (lane >> 2);
    const float inv0 = 1.f / l0, inv1 = 1.f / l1;
    const size_t row0 = (size_t)b_*SEQ + qt*128 + r0;
    #pragma unroll
    for (int nt = 0; nt < 8; nt++) {
        const int cc = nt*8 + 2*(lane & 3);
        *(uint32_t*)&g_a[row0*DMODEL + h_*HDIM + cc] =
            packh(o[nt][0]*inv0, o[nt][1]*inv0);
        *(uint32_t*)&g_a[(row0 + 8)*DMODEL + h_*HDIM + cc] =
            packh(o[nt][2]*inv1, o[nt][3]*inv1);
    }
}

// ---------------------------------------------------------------------------
extern "C" void kernel_launch(void* const* d_in, const int* in_sizes, int n_in,
                              void* d_out, int out_size)
{
    (void)in_sizes; (void)n_in; (void)out_size;
    const float* x  = (const float*)d_in[0];
    const float* Wq = (const float*)d_in[1];
    const float* bq = (const float*)d_in[2];
    const float* Wk = (const float*)d_in[3];
    const float* bk = (const float*)d_in[4];
    const float* Wv = (const float*)d_in[5];
    const float* bv = (const float*)d_in[6];
    const float* Wo = (const float*)d_in[7];
    const float* bo = (const float*)d_in[8];
    float* out = (float*)d_out;

    prep_x<<<(MROWS*DMODEL/4)/256, 256>>>(x);
    prep_wt<<<dim3(DMODEL/32, DMODEL/32, 4), 256>>>(Wq, Wk, Wv, Wo);

    cudaFuncSetAttribute(gemm_bf<0>, cudaFuncAttributeMaxDynamicSharedMemorySize, GEMM_SMEM);
    cudaFuncSetAttribute(gemm_bf<4>, cudaFuncAttributeMaxDynamicSharedMemorySize, GEMM_SMEM);
    cudaFuncSetAttribute(attn_bf, cudaFuncAttributeMaxDynamicSharedMemorySize, ATTN_SMEM);

    dim3 gq(MROWS/128, DMODEL/128, 3);   // fused QKV
    gemm_bf<0><<<gq, 256, GEMM_SMEM>>>(bq, bk, bv, nullptr);

    attn_bf<<<dim3(SEQ/128, BATCH*NHEAD), 256, ATTN_SMEM>>>();

    dim3 gg(MROWS/128, DMODEL/128);
    gemm_bf<4><<<gg, 256, GEMM_SMEM>>>(bo, nullptr, nullptr, out);
}